// round 1
// baseline (speedup 1.0000x reference)
#include <cuda_runtime.h>

// Decoder: 8 batches of 32-segment piecewise-linear functions sampled at
// 196608 uniform points. Output [8, 196608] fp32 (write-bound, 6.29 MB).

#define S_TOTAL 196608
#define NB 8
#define NSEG 32
#define NP1 33

__global__ __launch_bounds__(256) void decoder_pwl_kernel(
    const float* __restrict__ segx,
    const float* __restrict__ segy,
    float* __restrict__ out)
{
    __shared__ float xs[NB][NP1];   // fixed (running-max) knots
    __shared__ float ys[NB][NP1];   // carried y
    __shared__ float rs[NB][NSEG];  // per-segment slope

    const int t = threadIdx.x;
    if (t < NB) {
        // Sequential running-max "fix" of the knot order (33 steps).
        const float* px = segx + t * NP1;
        const float* py = segy + t * NP1;
        float rx = px[0];
        float ry = py[0];
        xs[t][0] = rx;
        ys[t][0] = ry;
#pragma unroll
        for (int i = 1; i < NP1; i++) {
            float xv = px[i];
            float yv = py[i];
            if (xv >= rx) { rx = xv; ry = yv; }  // ties take the later entry
            xs[t][i] = rx;
            ys[t][i] = ry;
        }
#pragma unroll
        for (int i = 0; i < NSEG; i++) {
            float d = xs[t][i + 1] - xs[t][i];
            if (d == 0.0f) d = 0.0001f;
            rs[t][i] = (ys[t][i + 1] - ys[t][i]) / d;
        }
    }
    __syncthreads();

    // One float4 (4 consecutive pixels of one batch row) per thread.
    const int tid4 = blockIdx.x * 256 + threadIdx.x;   // 0 .. 393215
    const int S4 = S_TOTAL / 4;                        // 49152
    const int b = tid4 / S4;
    const int s = (tid4 - b * S4) * 4;

    const float* bx = xs[b];
    const float* by = ys[b];
    const float* br = rs[b];

    // Segment index for the first pixel: largest j in [0,31] with bx[j] <= x_in.
    // (This single rule reproduces the reference's interior one-hot mask AND
    //  both clamp branches, since bx is non-decreasing.)
    const float x0 = (float)(s + 1) / (float)S_TOTAL;  // IEEE rn div, matches ref
    int j = 0;
#pragma unroll
    for (int step = 16; step >= 1; step >>= 1) {
        int nj = j + step;                             // nj <= 31 always
        if (bx[nj] <= x0) j = nj;
    }

    float ov[4];
#pragma unroll
    for (int e = 0; e < 4; e++) {
        float xin = (float)(s + 1 + e) / (float)S_TOTAL;
        // Advance segment for subsequent pixels (almost never iterates:
        // average segment width ~6000 pixels).
        while (j < NSEG - 1 && xin >= bx[j + 1]) j++;
        ov[e] = fmaf(br[j], xin - bx[j], by[j]);       // same arith order as ref
    }

    float4 o;
    o.x = ov[0]; o.y = ov[1]; o.z = ov[2]; o.w = ov[3];
    reinterpret_cast<float4*>(out)[tid4] = o;
}

extern "C" void kernel_launch(void* const* d_in, const int* in_sizes, int n_in,
                              void* d_out, int out_size) {
    const float* segx = (const float*)d_in[0];
    const float* segy = (const float*)d_in[1];
    float* out = (float*)d_out;

    // 8 * 196608 / 4 elements per thread-float4 = 393216 threads = 1536 blocks
    const int total4 = (NB * S_TOTAL) / 4;
    const int threads = 256;
    const int blocks = total4 / threads;  // 1536 exactly
    decoder_pwl_kernel<<<blocks, threads>>>(segx, segy, out);
}

// round 2
// speedup vs baseline: 3.3948x; 3.3948x over previous
#include <cuda_runtime.h>

// Decoder: 8 batches of 32-segment piecewise-linear functions sampled at
// 196608 uniform points. Output [8, 196608] fp32 = 6.29MB (fits in L2).
// Latency-bound -> register-cached coefficients, warp-scan prologue, no div.

#define S_TOTAL 196608
#define NB 8
#define NSEG 32
#define NP1 33
#define THREADS 128
#define ITERS 4                                    // float4s per thread
#define PIX_PER_BLOCK (THREADS * ITERS * 4)        // 2048
#define BLOCKS_PER_BATCH (S_TOTAL / PIX_PER_BLOCK) // 96

__global__ __launch_bounds__(THREADS) void decoder_pwl_kernel(
    const float* __restrict__ segx,
    const float* __restrict__ segy,
    float* __restrict__ out)
{
    __shared__ float xs[NP1];   // fixed (running-max) knots for this block's batch
    __shared__ float ys[NP1];   // carried y
    __shared__ float rs[NSEG];  // per-segment slope

    const int b = blockIdx.x / BLOCKS_PER_BATCH;
    const int chunk = blockIdx.x - b * BLOCKS_PER_BATCH;
    const int tid = threadIdx.x;

    // ---- Prologue: warp 0 does a parallel max-scan over the 33 knots ----
    if (tid < 32) {
        const int lane = tid;
        const float* px = segx + b * NP1;
        const float* py = segy + b * NP1;
        const float x0v = px[0];
        const float y0v = py[0];
        float xv = px[lane + 1];
        float yv = py[lane + 1];
        // Hillis-Steele inclusive scan of combine(a,b) = (later wins ties) argmax
        #pragma unroll
        for (int d = 1; d < 32; d <<= 1) {
            float ox = __shfl_up_sync(0xffffffffu, xv, d);
            float oy = __shfl_up_sync(0xffffffffu, yv, d);
            if (lane >= d && ox > xv) { xv = ox; yv = oy; }
        }
        // fold in knot 0 as the scan prefix
        if (x0v > xv) { xv = x0v; yv = y0v; }
        // previous knot (exclusive scan value) for slope computation
        float xp = __shfl_up_sync(0xffffffffu, xv, 1);
        float yp = __shfl_up_sync(0xffffffffu, yv, 1);
        if (lane == 0) { xp = x0v; yp = y0v; }
        float dd = xv - xp;
        if (dd == 0.0f) dd = 0.0001f;
        xs[lane] = xp;                 // knot l  (l = 0..31)
        ys[lane] = yp;
        rs[lane] = (yv - yp) / dd;     // slope of segment l
        if (lane == 31) { xs[32] = xv; ys[32] = yv; }
    }
    __syncthreads();

    // ---- Main: 16 pixels per thread, block-strided float4 writes ----
    const float inv = 1.0f / (float)S_TOTAL;   // <=1ulp vs IEEE div, tol is 1e-3
    const int s_first = chunk * PIX_PER_BLOCK + tid * 4;

    // largest j in [0,31] with xs[j] <= x_in  (handles both clamps too)
    const float xfirst = (float)(s_first + 1) * inv;
    int j = 0;
    #pragma unroll
    for (int step = 16; step >= 1; step >>= 1) {
        int nj = j + step;                     // <= 31 always
        if (xs[nj] <= xfirst) j = nj;
    }

    // register-cached segment coefficients (advance is rare: avg seg ~6000px)
    float c_x = xs[j], c_y = ys[j], c_r = rs[j];
    float c_nx = (j < NSEG - 1) ? xs[j + 1] : 3.4e38f;

    float4* out4 = reinterpret_cast<float4*>(out);
    const int obase = b * (S_TOTAL / 4) + chunk * (PIX_PER_BLOCK / 4) + tid;

    #pragma unroll
    for (int i = 0; i < ITERS; i++) {
        const int s = chunk * PIX_PER_BLOCK + (i * THREADS + tid) * 4;
        float4 o;
        float* ov = &o.x;
        #pragma unroll
        for (int e = 0; e < 4; e++) {
            float xin = (float)(s + 1 + e) * inv;
            while (xin >= c_nx) {              // monotonic advance, rarely taken
                j++;
                c_x = xs[j]; c_y = ys[j]; c_r = rs[j];
                c_nx = (j < NSEG - 1) ? xs[j + 1] : 3.4e38f;
            }
            ov[e] = fmaf(c_r, xin - c_x, c_y); // same arith order as reference
        }
        out4[obase + i * THREADS] = o;
    }
}

extern "C" void kernel_launch(void* const* d_in, const int* in_sizes, int n_in,
                              void* d_out, int out_size) {
    const float* segx = (const float*)d_in[0];
    const float* segy = (const float*)d_in[1];
    float* out = (float*)d_out;

    const int blocks = NB * BLOCKS_PER_BATCH;  // 768
    decoder_pwl_kernel<<<blocks, THREADS>>>(segx, segy, out);
}